// round 13
// baseline (speedup 1.0000x reference)
#include <cuda_runtime.h>
#include <cuda_bf16.h>
#include <math.h>

// Problem constants
#define B_    32
#define LQ    300
#define DM    256
#define NH    8
#define HD    32
#define TOTAL 12          // 3 levels x 4 points
#define S_    8400        // 80*80 + 40*40 + 20*20
#define NOFF  (NH * TOTAL * 2)   // 192
#define NATT  (NH * TOTAL)       // 96
#define NCOL  (NOFF + NATT)      // 288

// GEMM tiling
#define BM 64
#define BN 96
#define BK 16
#define QS_STRIDE 68      // 64 + pad4

typedef unsigned long long ull;

// Scratch
__device__ float g_res[B_ * LQ * NCOL];             // projection outputs (9600 x 288)
__device__ int2  g_desc[B_ * LQ * NH * TOTAL * 4];  // [(task)*48 + p*4 + corner] = {elem offset, weight bits}

__device__ __forceinline__ ull pack2(float lo, float hi) {
    ull r; asm("mov.b64 %0, {%1, %2};" : "=l"(r) : "f"(lo), "f"(hi)); return r;
}
__device__ __forceinline__ void unpack2(ull v, float& lo, float& hi) {
    asm("mov.b64 {%0, %1}, %2;" : "=f"(lo), "=f"(hi) : "l"(v));
}
__device__ __forceinline__ ull fma2(ull a, ull b, ull c) {
    ull d; asm("fma.rn.f32x2 %0, %1, %2, %3;" : "=l"(d) : "l"(a), "l"(b), "l"(c)); return d;
}

// ---------------------------------------------------------------------------
// Kernel A: tiled SGEMM  C[9600,288] = Q[9600,256] * W[256,288] + bias
// Ws stored duplicated {w,w}: inner loop reads packed LDS.64 directly.
// launch_bounds minor bound = 3 so no register spills (regs ~80).
// ---------------------------------------------------------------------------
__global__ __launch_bounds__(256, 3)
void gemm_kernel(const float* __restrict__ q,
                 const float* __restrict__ Woff,    // (256,192)
                 const float* __restrict__ boff,
                 const float* __restrict__ Wattn,   // (256,96)
                 const float* __restrict__ battn)
{
    const int t   = threadIdx.x;
    const int bm0 = blockIdx.x * BM;
    const int bn  = blockIdx.y;                  // 0,1 -> Woff halves; 2 -> Wattn

    __shared__ __align__(16) float Qs[2][BK * QS_STRIDE];
    __shared__ __align__(8)  float Ws[2][BK * BN * 2];   // duplicated pairs

    const float* Wg; int wstride; const float* bg;
    if (bn < 2) { Wg = Woff + bn * BN; wstride = NOFF; bg = boff + bn * BN; }
    else        { Wg = Wattn;          wstride = NATT; bg = battn; }

    const int tn = t & 31;           // col lane
    const int tm = t >> 5;           // row group (0..7), 8 rows each

    int wk[6], wn[6];
    #pragma unroll
    for (int i = 0; i < 6; i++) {
        const int flat = t + i * 256;
        wk[i] = flat / BN;
        wn[i] = flat - wk[i] * BN;
    }
    const int qr  = t >> 2;          // row 0..63
    const int qc4 = t & 3;           // k-chunk-of-4

    ull acc[3][4];
    #pragma unroll
    for (int j = 0; j < 3; j++) {
        const float b = bg[tn + 32 * j];
        const ull b2 = pack2(b, b);
        #pragma unroll
        for (int pi = 0; pi < 4; pi++) acc[j][pi] = b2;
    }

    float4 rq = *(const float4*)(q + (size_t)(bm0 + qr) * DM + qc4 * 4);
    float rw[6];
    #pragma unroll
    for (int i = 0; i < 6; i++) rw[i] = Wg[wk[i] * wstride + wn[i]];

    Qs[0][(qc4 * 4 + 0) * QS_STRIDE + qr] = rq.x;
    Qs[0][(qc4 * 4 + 1) * QS_STRIDE + qr] = rq.y;
    Qs[0][(qc4 * 4 + 2) * QS_STRIDE + qr] = rq.z;
    Qs[0][(qc4 * 4 + 3) * QS_STRIDE + qr] = rq.w;
    #pragma unroll
    for (int i = 0; i < 6; i++)
        *(float2*)&Ws[0][(wk[i] * BN + wn[i]) * 2] = make_float2(rw[i], rw[i]);
    __syncthreads();

    const int NCH = DM / BK;         // 16 chunks
    for (int ch = 0; ch < NCH; ch++) {
        const int cur = ch & 1;

        if (ch + 1 < NCH) {
            const int k0 = (ch + 1) * BK;
            rq = *(const float4*)(q + (size_t)(bm0 + qr) * DM + k0 + qc4 * 4);
            #pragma unroll
            for (int i = 0; i < 6; i++) rw[i] = Wg[(k0 + wk[i]) * wstride + wn[i]];
        }

        #pragma unroll
        for (int kk = 0; kk < BK; kk++) {
            const float* qrow = Qs[cur] + kk * QS_STRIDE + tm * 8;
            const ulonglong2 qa = *(const ulonglong2*)qrow;
            const ulonglong2 qb = *(const ulonglong2*)(qrow + 4);
            #pragma unroll
            for (int j = 0; j < 3; j++) {
                const ull wp = *(const ull*)&Ws[cur][(kk * BN + tn + 32 * j) * 2];
                acc[j][0] = fma2(qa.x, wp, acc[j][0]);
                acc[j][1] = fma2(qa.y, wp, acc[j][1]);
                acc[j][2] = fma2(qb.x, wp, acc[j][2]);
                acc[j][3] = fma2(qb.y, wp, acc[j][3]);
            }
        }

        if (ch + 1 < NCH) {
            const int nxt = cur ^ 1;
            Qs[nxt][(qc4 * 4 + 0) * QS_STRIDE + qr] = rq.x;
            Qs[nxt][(qc4 * 4 + 1) * QS_STRIDE + qr] = rq.y;
            Qs[nxt][(qc4 * 4 + 2) * QS_STRIDE + qr] = rq.z;
            Qs[nxt][(qc4 * 4 + 3) * QS_STRIDE + qr] = rq.w;
            #pragma unroll
            for (int i = 0; i < 6; i++)
                *(float2*)&Ws[nxt][(wk[i] * BN + wn[i]) * 2] = make_float2(rw[i], rw[i]);
            __syncthreads();
        }
    }

    // epilogue
    #pragma unroll
    for (int j = 0; j < 3; j++) {
        const int n = bn * BN + tn + 32 * j;
        #pragma unroll
        for (int pi = 0; pi < 4; pi++) {
            float lo, hi; unpack2(acc[j][pi], lo, hi);
            const int m = bm0 + tm * 8 + 2 * pi;
            g_res[(size_t)m       * NCOL + n] = lo;
            g_res[(size_t)(m + 1) * NCOL + n] = hi;
        }
    }
}

// ---------------------------------------------------------------------------
// Kernel B: softmax + FINAL sampling descriptors. One thread per (bq, h).
// Writes {element offset, premultiplied weight} per (point, corner).
// ---------------------------------------------------------------------------
__global__ __launch_bounds__(256)
void desc_kernel(const float* __restrict__ ref)    // (B,Lq,1,4)
{
    const int tid = blockIdx.x * blockDim.x + threadIdx.x;
    if (tid >= B_ * LQ * NH) return;
    const int bq = tid >> 3;
    const int h  = tid & 7;
    const int b  = bq / LQ;

    const float4 r4 = __ldg((const float4*)(ref + (size_t)bq * 4));
    const float* row = g_res + (size_t)bq * NCOL;

    float a[TOTAL];
    float m = -1e30f;
    #pragma unroll
    for (int p = 0; p < TOTAL; p++) { a[p] = row[NOFF + h * TOTAL + p]; m = fmaxf(m, a[p]); }
    float s = 0.f;
    #pragma unroll
    for (int p = 0; p < TOTAL; p++) { a[p] = __expf(a[p] - m); s += a[p]; }
    const float inv = 1.0f / s;

    int2* dst = g_desc + (size_t)tid * TOTAL * 4;

    #pragma unroll
    for (int p = 0; p < TOTAL; p++) {
        const float offx = row[h * (TOTAL * 2) + 2 * p];
        const float offy = row[h * (TOTAL * 2) + 2 * p + 1];
        const float wt   = a[p] * inv;

        const float lx = fmaf(offx * 0.125f, r4.z, r4.x);
        const float ly = fmaf(offy * 0.125f, r4.w, r4.y);

        const int lvl = p >> 2;
        const int W   = 80 >> lvl;
        const int st  = (lvl == 0) ? 0 : ((lvl == 1) ? 6400 : 8000);

        const float ix = lx * (float)W - 0.5f;
        const float iy = ly * (float)W - 0.5f;
        const float fix = floorf(ix);
        const float fiy = floorf(iy);
        const int x0 = (int)fix, y0 = (int)fiy;
        const float fx = ix - fix;
        const float fy = iy - fiy;

        const bool vx0 = (x0 >= 0)  & (x0 < W);
        const bool vx1 = (x0 >= -1) & (x0 < W - 1);
        const bool vy0 = (y0 >= 0)  & (y0 < W);
        const bool vy1 = (y0 >= -1) & (y0 < W - 1);

        const int xc0 = min(max(x0, 0),     W - 1);
        const int xc1 = min(max(x0 + 1, 0), W - 1);
        const int yc0 = min(max(y0, 0),     W - 1);
        const int yc1 = min(max(y0 + 1, 0), W - 1);

        const int base = b * S_ + st;
        const int i00 = (base + yc0 * W + xc0) * DM;
        const int i01 = (base + yc0 * W + xc1) * DM;
        const int i10 = (base + yc1 * W + xc0) * DM;
        const int i11 = (base + yc1 * W + xc1) * DM;

        const float fx0 = vx0 ? (1.f - fx) : 0.f;
        const float fx1 = vx1 ? fx         : 0.f;
        const float fy0 = (vy0 ? (1.f - fy) : 0.f) * wt;
        const float fy1 = (vy1 ? fy         : 0.f) * wt;

        dst[p * 4 + 0] = make_int2(i00, __float_as_int(fx0 * fy0));
        dst[p * 4 + 1] = make_int2(i01, __float_as_int(fx1 * fy0));
        dst[p * 4 + 2] = make_int2(i10, __float_as_int(fx0 * fy1));
        dst[p * 4 + 3] = make_int2(i11, __float_as_int(fx1 * fy1));
    }
}

// ---------------------------------------------------------------------------
// Kernel C: pure gather. Block = 8 tasks (one bq); stage descriptors with
// coalesced int4 loads; warp = head, lane = 8*corner + channel-quad.
// Inner loop: LDS.64 + LDG.128 + 4 FMA per point.
// ---------------------------------------------------------------------------
__global__ __launch_bounds__(256)
void sample_kernel(const float* __restrict__ val,   // input_flatten (B,S,256)
                   float* __restrict__ out)
{
    __shared__ int2 sdw[8 * TOTAL * 4];    // 8 tasks x 48 pairs = 3 KB

    const int t     = threadIdx.x;
    const int task0 = blockIdx.x * 8;

    // stage 384 int2 = 192 int4, coalesced
    {
        const int4* src = (const int4*)(g_desc + (size_t)task0 * TOTAL * 4);
        int4* dst = (int4*)sdw;
        if (t < 192) dst[t] = __ldg(src + t);
    }
    __syncthreads();

    const int w    = t >> 5;        // task within block (= head)
    const int lane = t & 31;
    const int task = task0 + w;
    const int h    = task & 7;

    const int g = lane >> 3;        // corner 0..3
    const int r = lane & 7;         // channel quad 0..7

    const float* vch = val + h * HD + 4 * r;
    const int2* dbase = sdw + w * TOTAL * 4 + g;

    float4 acc = make_float4(0.f, 0.f, 0.f, 0.f);

    #pragma unroll
    for (int p = 0; p < TOTAL; p++) {
        const int2 dw = dbase[p * 4];
        const float wg = __int_as_float(dw.y);
        const float4 v = __ldg((const float4*)(vch + dw.x));
        acc.x = fmaf(wg, v.x, acc.x);
        acc.y = fmaf(wg, v.y, acc.y);
        acc.z = fmaf(wg, v.z, acc.z);
        acc.w = fmaf(wg, v.w, acc.w);
    }

    // reduce across the 4 corner groups
    #pragma unroll
    for (int mask = 8; mask <= 16; mask <<= 1) {
        acc.x += __shfl_xor_sync(0xffffffffu, acc.x, mask);
        acc.y += __shfl_xor_sync(0xffffffffu, acc.y, mask);
        acc.z += __shfl_xor_sync(0xffffffffu, acc.z, mask);
        acc.w += __shfl_xor_sync(0xffffffffu, acc.w, mask);
    }

    if (lane < 8)
        *(float4*)(out + (size_t)(task >> 3) * DM + h * HD + 4 * lane) = acc;
}

// ---------------------------------------------------------------------------
// Launch
// ---------------------------------------------------------------------------
extern "C" void kernel_launch(void* const* d_in, const int* in_sizes, int n_in,
                              void* d_out, int out_size)
{
    const float* query = (const float*)d_in[0];
    const float* ref   = (const float*)d_in[1];
    const float* value = (const float*)d_in[2];
    const float* Woff  = (const float*)d_in[3];
    const float* boff  = (const float*)d_in[4];
    const float* Wattn = (const float*)d_in[5];
    const float* battn = (const float*)d_in[6];
    float* out = (float*)d_out;

    dim3 ggrid(B_ * LQ / BM, 3);                     // 150 x 3
    gemm_kernel<<<ggrid, 256>>>(query, Woff, boff, Wattn, battn);

    desc_kernel<<<(B_ * LQ * NH + 255) / 256, 256>>>(ref);

    sample_kernel<<<B_ * LQ, 256>>>(value, out);     // 9600 blocks, 8 tasks each
}

// round 14
// speedup vs baseline: 1.0547x; 1.0547x over previous
#include <cuda_runtime.h>
#include <cuda_bf16.h>
#include <math.h>

// Problem constants
#define B_    32
#define LQ    300
#define DM    256
#define NH    8
#define HD    32
#define TOTAL 12          // 3 levels x 4 points
#define S_    8400        // 80*80 + 40*40 + 20*20
#define NOFF  (NH * TOTAL * 2)   // 192
#define NATT  (NH * TOTAL)       // 96
#define NCOL  (NOFF + NATT)      // 288

// GEMM tiling
#define BM 64
#define BN 96
#define BK 16
#define QS_STRIDE 68      // 64 + pad4

typedef unsigned long long ull;

// Scratch
__device__ float g_res[B_ * LQ * NCOL];             // projection outputs (9600 x 288)
__device__ int2  g_desc[B_ * LQ * NH * TOTAL * 4];  // [(task)*48 + p*4 + corner] = {elem offset, weight bits}

__device__ __forceinline__ ull pack2(float lo, float hi) {
    ull r; asm("mov.b64 %0, {%1, %2};" : "=l"(r) : "f"(lo), "f"(hi)); return r;
}
__device__ __forceinline__ void unpack2(ull v, float& lo, float& hi) {
    asm("mov.b64 {%0, %1}, %2;" : "=f"(lo), "=f"(hi) : "l"(v));
}
__device__ __forceinline__ ull fma2(ull a, ull b, ull c) {
    ull d; asm("fma.rn.f32x2 %0, %1, %2, %3;" : "=l"(d) : "l"(a), "l"(b), "l"(c)); return d;
}

// ---------------------------------------------------------------------------
// Kernel A: tiled SGEMM  C[9600,288] = Q[9600,256] * W[256,288] + bias
// (R8-measured config: double-buffered, scalar Ws LDS.32, regs=80, 37us)
// ---------------------------------------------------------------------------
__global__ __launch_bounds__(256, 3)
void gemm_kernel(const float* __restrict__ q,
                 const float* __restrict__ Woff,    // (256,192)
                 const float* __restrict__ boff,
                 const float* __restrict__ Wattn,   // (256,96)
                 const float* __restrict__ battn)
{
    const int t   = threadIdx.x;
    const int bm0 = blockIdx.x * BM;
    const int bn  = blockIdx.y;                  // 0,1 -> Woff halves; 2 -> Wattn

    __shared__ __align__(16) float Qs[2][BK * QS_STRIDE];
    __shared__ float Ws[2][BK * BN];

    const float* Wg; int wstride; const float* bg;
    if (bn < 2) { Wg = Woff + bn * BN; wstride = NOFF; bg = boff + bn * BN; }
    else        { Wg = Wattn;          wstride = NATT; bg = battn; }

    const int tn = t & 31;           // col lane
    const int tm = t >> 5;           // row group (0..7), 8 rows each

    int wk[6], wn[6];
    #pragma unroll
    for (int i = 0; i < 6; i++) {
        const int flat = t + i * 256;
        wk[i] = flat / BN;
        wn[i] = flat - wk[i] * BN;
    }
    const int qr  = t >> 2;          // row 0..63
    const int qc4 = t & 3;           // k-chunk-of-4

    ull acc[3][4];
    #pragma unroll
    for (int j = 0; j < 3; j++) {
        const float b = bg[tn + 32 * j];
        const ull b2 = pack2(b, b);
        #pragma unroll
        for (int pi = 0; pi < 4; pi++) acc[j][pi] = b2;
    }

    float4 rq = *(const float4*)(q + (size_t)(bm0 + qr) * DM + qc4 * 4);
    float rw[6];
    #pragma unroll
    for (int i = 0; i < 6; i++) rw[i] = Wg[wk[i] * wstride + wn[i]];

    Qs[0][(qc4 * 4 + 0) * QS_STRIDE + qr] = rq.x;
    Qs[0][(qc4 * 4 + 1) * QS_STRIDE + qr] = rq.y;
    Qs[0][(qc4 * 4 + 2) * QS_STRIDE + qr] = rq.z;
    Qs[0][(qc4 * 4 + 3) * QS_STRIDE + qr] = rq.w;
    #pragma unroll
    for (int i = 0; i < 6; i++) Ws[0][wk[i] * BN + wn[i]] = rw[i];
    __syncthreads();

    const int NCH = DM / BK;         // 16 chunks
    for (int ch = 0; ch < NCH; ch++) {
        const int cur = ch & 1;

        if (ch + 1 < NCH) {
            const int k0 = (ch + 1) * BK;
            rq = *(const float4*)(q + (size_t)(bm0 + qr) * DM + k0 + qc4 * 4);
            #pragma unroll
            for (int i = 0; i < 6; i++) rw[i] = Wg[(k0 + wk[i]) * wstride + wn[i]];
        }

        #pragma unroll
        for (int kk = 0; kk < BK; kk++) {
            const float* qrow = Qs[cur] + kk * QS_STRIDE + tm * 8;
            const ulonglong2 qa = *(const ulonglong2*)qrow;
            const ulonglong2 qb = *(const ulonglong2*)(qrow + 4);
            #pragma unroll
            for (int j = 0; j < 3; j++) {
                const float w = Ws[cur][kk * BN + tn + 32 * j];
                const ull  wp = pack2(w, w);
                acc[j][0] = fma2(qa.x, wp, acc[j][0]);
                acc[j][1] = fma2(qa.y, wp, acc[j][1]);
                acc[j][2] = fma2(qb.x, wp, acc[j][2]);
                acc[j][3] = fma2(qb.y, wp, acc[j][3]);
            }
        }

        if (ch + 1 < NCH) {
            const int nxt = cur ^ 1;
            Qs[nxt][(qc4 * 4 + 0) * QS_STRIDE + qr] = rq.x;
            Qs[nxt][(qc4 * 4 + 1) * QS_STRIDE + qr] = rq.y;
            Qs[nxt][(qc4 * 4 + 2) * QS_STRIDE + qr] = rq.z;
            Qs[nxt][(qc4 * 4 + 3) * QS_STRIDE + qr] = rq.w;
            #pragma unroll
            for (int i = 0; i < 6; i++) Ws[nxt][wk[i] * BN + wn[i]] = rw[i];
            __syncthreads();
        }
    }

    // epilogue
    #pragma unroll
    for (int j = 0; j < 3; j++) {
        const int n = bn * BN + tn + 32 * j;
        #pragma unroll
        for (int pi = 0; pi < 4; pi++) {
            float lo, hi; unpack2(acc[j][pi], lo, hi);
            const int m = bm0 + tm * 8 + 2 * pi;
            g_res[(size_t)m       * NCOL + n] = lo;
            g_res[(size_t)(m + 1) * NCOL + n] = hi;
        }
    }
}

// ---------------------------------------------------------------------------
// Kernel B: softmax + FINAL sampling descriptors. One thread per (bq, h).
// ---------------------------------------------------------------------------
__global__ __launch_bounds__(256)
void desc_kernel(const float* __restrict__ ref)    // (B,Lq,1,4)
{
    const int tid = blockIdx.x * blockDim.x + threadIdx.x;
    if (tid >= B_ * LQ * NH) return;
    const int bq = tid >> 3;
    const int h  = tid & 7;
    const int b  = bq / LQ;

    const float4 r4 = __ldg((const float4*)(ref + (size_t)bq * 4));
    const float* row = g_res + (size_t)bq * NCOL;

    float a[TOTAL];
    float m = -1e30f;
    #pragma unroll
    for (int p = 0; p < TOTAL; p++) { a[p] = row[NOFF + h * TOTAL + p]; m = fmaxf(m, a[p]); }
    float s = 0.f;
    #pragma unroll
    for (int p = 0; p < TOTAL; p++) { a[p] = __expf(a[p] - m); s += a[p]; }
    const float inv = 1.0f / s;

    int2* dst = g_desc + (size_t)tid * TOTAL * 4;

    #pragma unroll
    for (int p = 0; p < TOTAL; p++) {
        const float offx = row[h * (TOTAL * 2) + 2 * p];
        const float offy = row[h * (TOTAL * 2) + 2 * p + 1];
        const float wt   = a[p] * inv;

        const float lx = fmaf(offx * 0.125f, r4.z, r4.x);
        const float ly = fmaf(offy * 0.125f, r4.w, r4.y);

        const int lvl = p >> 2;
        const int W   = 80 >> lvl;
        const int st  = (lvl == 0) ? 0 : ((lvl == 1) ? 6400 : 8000);

        const float ix = lx * (float)W - 0.5f;
        const float iy = ly * (float)W - 0.5f;
        const float fix = floorf(ix);
        const float fiy = floorf(iy);
        const int x0 = (int)fix, y0 = (int)fiy;
        const float fx = ix - fix;
        const float fy = iy - fiy;

        const bool vx0 = (x0 >= 0)  & (x0 < W);
        const bool vx1 = (x0 >= -1) & (x0 < W - 1);
        const bool vy0 = (y0 >= 0)  & (y0 < W);
        const bool vy1 = (y0 >= -1) & (y0 < W - 1);

        const int xc0 = min(max(x0, 0),     W - 1);
        const int xc1 = min(max(x0 + 1, 0), W - 1);
        const int yc0 = min(max(y0, 0),     W - 1);
        const int yc1 = min(max(y0 + 1, 0), W - 1);

        const int base = b * S_ + st;
        const int i00 = (base + yc0 * W + xc0) * DM;
        const int i01 = (base + yc0 * W + xc1) * DM;
        const int i10 = (base + yc1 * W + xc0) * DM;
        const int i11 = (base + yc1 * W + xc1) * DM;

        const float fx0 = vx0 ? (1.f - fx) : 0.f;
        const float fx1 = vx1 ? fx         : 0.f;
        const float fy0 = (vy0 ? (1.f - fy) : 0.f) * wt;
        const float fy1 = (vy1 ? fy         : 0.f) * wt;

        dst[p * 4 + 0] = make_int2(i00, __float_as_int(fx0 * fy0));
        dst[p * 4 + 1] = make_int2(i01, __float_as_int(fx1 * fy0));
        dst[p * 4 + 2] = make_int2(i10, __float_as_int(fx0 * fy1));
        dst[p * 4 + 3] = make_int2(i11, __float_as_int(fx1 * fy1));
    }
}

// ---------------------------------------------------------------------------
// Kernel C: pure gather with forced MLP. Block = 8 tasks (one bq).
// Per thread: preload all 12 descriptors -> issue all 12 LDG.128 -> 48 FMA.
// ---------------------------------------------------------------------------
__global__ __launch_bounds__(256)
void sample_kernel(const float* __restrict__ val,   // input_flatten (B,S,256)
                   float* __restrict__ out)
{
    __shared__ int2 sdw[8 * TOTAL * 4];    // 8 tasks x 48 pairs = 3 KB

    const int t     = threadIdx.x;
    const int task0 = blockIdx.x * 8;

    // stage 384 int2 = 192 int4, coalesced
    {
        const int4* src = (const int4*)(g_desc + (size_t)task0 * TOTAL * 4);
        int4* dst = (int4*)sdw;
        if (t < 192) dst[t] = __ldg(src + t);
    }
    __syncthreads();

    const int w    = t >> 5;        // task within block (= head)
    const int lane = t & 31;
    const int task = task0 + w;
    const int h    = task & 7;

    const int g = lane >> 3;        // corner 0..3
    const int r = lane & 7;         // channel quad 0..7

    const float* vch = val + h * HD + 4 * r;
    const int2* dbase = sdw + w * TOTAL * 4 + g;

    // 1) preload all descriptors into registers
    int2 dw[TOTAL];
    #pragma unroll
    for (int p = 0; p < TOTAL; p++) dw[p] = dbase[p * 4];

    // 2) issue all 12 independent LDG.128s (max MLP)
    float4 v[TOTAL];
    #pragma unroll
    for (int p = 0; p < TOTAL; p++) v[p] = __ldg((const float4*)(vch + dw[p].x));

    // 3) accumulate
    float4 acc = make_float4(0.f, 0.f, 0.f, 0.f);
    #pragma unroll
    for (int p = 0; p < TOTAL; p++) {
        const float wg = __int_as_float(dw[p].y);
        acc.x = fmaf(wg, v[p].x, acc.x);
        acc.y = fmaf(wg, v[p].y, acc.y);
        acc.z = fmaf(wg, v[p].z, acc.z);
        acc.w = fmaf(wg, v[p].w, acc.w);
    }

    // reduce across the 4 corner groups
    #pragma unroll
    for (int mask = 8; mask <= 16; mask <<= 1) {
        acc.x += __shfl_xor_sync(0xffffffffu, acc.x, mask);
        acc.y += __shfl_xor_sync(0xffffffffu, acc.y, mask);
        acc.z += __shfl_xor_sync(0xffffffffu, acc.z, mask);
        acc.w += __shfl_xor_sync(0xffffffffu, acc.w, mask);
    }

    if (lane < 8)
        *(float4*)(out + (size_t)(task >> 3) * DM + h * HD + 4 * lane) = acc;
}

// ---------------------------------------------------------------------------
// Launch
// ---------------------------------------------------------------------------
extern "C" void kernel_launch(void* const* d_in, const int* in_sizes, int n_in,
                              void* d_out, int out_size)
{
    const float* query = (const float*)d_in[0];
    const float* ref   = (const float*)d_in[1];
    const float* value = (const float*)d_in[2];
    const float* Woff  = (const float*)d_in[3];
    const float* boff  = (const float*)d_in[4];
    const float* Wattn = (const float*)d_in[5];
    const float* battn = (const float*)d_in[6];
    float* out = (float*)d_out;

    dim3 ggrid(B_ * LQ / BM, 3);                     // 150 x 3
    gemm_kernel<<<ggrid, 256>>>(query, Woff, boff, Wattn, battn);

    desc_kernel<<<(B_ * LQ * NH + 255) / 256, 256>>>(ref);

    sample_kernel<<<B_ * LQ, 256>>>(value, out);     // 9600 blocks, 8 tasks each
}

// round 16
// speedup vs baseline: 1.2856x; 1.2189x over previous
#include <cuda_runtime.h>
#include <cuda_bf16.h>
#include <math.h>

// Problem constants
#define B_    32
#define LQ    300
#define DM    256
#define NH    8
#define HD    32
#define TOTAL 12          // 3 levels x 4 points
#define S_    8400        // 80*80 + 40*40 + 20*20
#define NOFF  (NH * TOTAL * 2)   // 192
#define NATT  (NH * TOTAL)       // 96
#define NCOL  (NOFF + NATT)      // 288

// GEMM tiling
#define BM 64
#define BN 96
#define BK 16
#define QS_STRIDE 68      // 64 + pad4

typedef unsigned long long ull;

// Scratch
__device__ float g_res[B_ * LQ * NCOL];   // projection outputs (9600 x 288)

__device__ __forceinline__ ull pack2(float lo, float hi) {
    ull r; asm("mov.b64 %0, {%1, %2};" : "=l"(r) : "f"(lo), "f"(hi)); return r;
}
__device__ __forceinline__ void unpack2(ull v, float& lo, float& hi) {
    asm("mov.b64 {%0, %1}, %2;" : "=f"(lo), "=f"(hi) : "l"(v));
}
__device__ __forceinline__ ull fma2(ull a, ull b, ull c) {
    ull d; asm("fma.rn.f32x2 %0, %1, %2, %3;" : "=l"(d) : "l"(a), "l"(b), "l"(c)); return d;
}

// ---------------------------------------------------------------------------
// Kernel A: tiled SGEMM  C[9600,288] = Q[9600,256] * W[256,288] + bias
// (R8-measured config: double-buffered, scalar Ws LDS.32, regs=80, ~37.5us)
// ---------------------------------------------------------------------------
__global__ __launch_bounds__(256, 3)
void gemm_kernel(const float* __restrict__ q,
                 const float* __restrict__ Woff,    // (256,192)
                 const float* __restrict__ boff,
                 const float* __restrict__ Wattn,   // (256,96)
                 const float* __restrict__ battn)
{
    const int t   = threadIdx.x;
    const int bm0 = blockIdx.x * BM;
    const int bn  = blockIdx.y;                  // 0,1 -> Woff halves; 2 -> Wattn

    __shared__ __align__(16) float Qs[2][BK * QS_STRIDE];
    __shared__ float Ws[2][BK * BN];

    const float* Wg; int wstride; const float* bg;
    if (bn < 2) { Wg = Woff + bn * BN; wstride = NOFF; bg = boff + bn * BN; }
    else        { Wg = Wattn;          wstride = NATT; bg = battn; }

    const int tn = t & 31;           // col lane
    const int tm = t >> 5;           // row group (0..7), 8 rows each

    int wk[6], wn[6];
    #pragma unroll
    for (int i = 0; i < 6; i++) {
        const int flat = t + i * 256;
        wk[i] = flat / BN;
        wn[i] = flat - wk[i] * BN;
    }
    const int qr  = t >> 2;          // row 0..63
    const int qc4 = t & 3;           // k-chunk-of-4

    ull acc[3][4];
    #pragma unroll
    for (int j = 0; j < 3; j++) {
        const float b = bg[tn + 32 * j];
        const ull b2 = pack2(b, b);
        #pragma unroll
        for (int pi = 0; pi < 4; pi++) acc[j][pi] = b2;
    }

    float4 rq = *(const float4*)(q + (size_t)(bm0 + qr) * DM + qc4 * 4);
    float rw[6];
    #pragma unroll
    for (int i = 0; i < 6; i++) rw[i] = Wg[wk[i] * wstride + wn[i]];

    Qs[0][(qc4 * 4 + 0) * QS_STRIDE + qr] = rq.x;
    Qs[0][(qc4 * 4 + 1) * QS_STRIDE + qr] = rq.y;
    Qs[0][(qc4 * 4 + 2) * QS_STRIDE + qr] = rq.z;
    Qs[0][(qc4 * 4 + 3) * QS_STRIDE + qr] = rq.w;
    #pragma unroll
    for (int i = 0; i < 6; i++) Ws[0][wk[i] * BN + wn[i]] = rw[i];
    __syncthreads();

    const int NCH = DM / BK;         // 16 chunks
    for (int ch = 0; ch < NCH; ch++) {
        const int cur = ch & 1;

        if (ch + 1 < NCH) {
            const int k0 = (ch + 1) * BK;
            rq = *(const float4*)(q + (size_t)(bm0 + qr) * DM + k0 + qc4 * 4);
            #pragma unroll
            for (int i = 0; i < 6; i++) rw[i] = Wg[(k0 + wk[i]) * wstride + wn[i]];
        }

        #pragma unroll
        for (int kk = 0; kk < BK; kk++) {
            const float* qrow = Qs[cur] + kk * QS_STRIDE + tm * 8;
            const ulonglong2 qa = *(const ulonglong2*)qrow;
            const ulonglong2 qb = *(const ulonglong2*)(qrow + 4);
            #pragma unroll
            for (int j = 0; j < 3; j++) {
                const float w = Ws[cur][kk * BN + tn + 32 * j];
                const ull  wp = pack2(w, w);
                acc[j][0] = fma2(qa.x, wp, acc[j][0]);
                acc[j][1] = fma2(qa.y, wp, acc[j][1]);
                acc[j][2] = fma2(qb.x, wp, acc[j][2]);
                acc[j][3] = fma2(qb.y, wp, acc[j][3]);
            }
        }

        if (ch + 1 < NCH) {
            const int nxt = cur ^ 1;
            Qs[nxt][(qc4 * 4 + 0) * QS_STRIDE + qr] = rq.x;
            Qs[nxt][(qc4 * 4 + 1) * QS_STRIDE + qr] = rq.y;
            Qs[nxt][(qc4 * 4 + 2) * QS_STRIDE + qr] = rq.z;
            Qs[nxt][(qc4 * 4 + 3) * QS_STRIDE + qr] = rq.w;
            #pragma unroll
            for (int i = 0; i < 6; i++) Ws[nxt][wk[i] * BN + wn[i]] = rw[i];
            __syncthreads();
        }
    }

    // epilogue
    #pragma unroll
    for (int j = 0; j < 3; j++) {
        const int n = bn * BN + tn + 32 * j;
        #pragma unroll
        for (int pi = 0; pi < 4; pi++) {
            float lo, hi; unpack2(acc[j][pi], lo, hi);
            const int m = bm0 + tm * 8 + 2 * pi;
            g_res[(size_t)m       * NCOL + n] = lo;
            g_res[(size_t)(m + 1) * NCOL + n] = hi;
        }
    }
}

// ---------------------------------------------------------------------------
// Kernel B: fused descriptors + gather. One block per bq (8 warps = 8 heads).
// Desc phase -> FINAL {offset, weight} pairs in smem. Gather processes points
// in groups of 4 (MLP=4: below the L1tex queue-contention cliff).
// ---------------------------------------------------------------------------
__global__ __launch_bounds__(256)
void sample_kernel(const float* __restrict__ val,   // input_flatten (B,S,256)
                   const float* __restrict__ ref,   // (B,Lq,1,4)
                   float* __restrict__ out)
{
    __shared__ float  sres[NCOL];
    __shared__ float  ssm[NH][2];          // per-head {max, 1/sum}
    __shared__ int2   sdw[NATT * 4];       // [(h*12+p)*4+corner] = {offset, w_bits}

    const int t  = threadIdx.x;
    const int bq = blockIdx.x;
    const int b  = bq / LQ;

    // stage projection row (coalesced)
    for (int i = t; i < NCOL; i += 256)
        sres[i] = __ldg(&g_res[(size_t)bq * NCOL + i]);
    __syncthreads();

    // per-head softmax denominators (threads 0..7)
    if (t < NH) {
        const float* lg = sres + NOFF + t * TOTAL;
        float m = -1e30f;
        #pragma unroll
        for (int i = 0; i < TOTAL; i++) m = fmaxf(m, lg[i]);
        float s = 0.f;
        #pragma unroll
        for (int i = 0; i < TOTAL; i++) s += __expf(lg[i] - m);
        ssm[t][0] = m;
        ssm[t][1] = 1.0f / s;
    }
    __syncthreads();

    // descriptors: thread t < 96 handles (h = t/12, p = t%12)
    if (t < NATT) {
        const int h = t / TOTAL;
        const int p = t - h * TOTAL;

        const float4 r4 = __ldg((const float4*)(ref + (size_t)bq * 4));
        const float wt = __expf(sres[NOFF + t] - ssm[h][0]) * ssm[h][1];

        const float offx = sres[h * (TOTAL * 2) + 2 * p];
        const float offy = sres[h * (TOTAL * 2) + 2 * p + 1];

        const float lx = fmaf(offx * 0.125f, r4.z, r4.x);
        const float ly = fmaf(offy * 0.125f, r4.w, r4.y);

        const int lvl = p >> 2;
        const int W   = 80 >> lvl;
        const int st  = (lvl == 0) ? 0 : ((lvl == 1) ? 6400 : 8000);

        const float ix = lx * (float)W - 0.5f;
        const float iy = ly * (float)W - 0.5f;
        const float fix = floorf(ix);
        const float fiy = floorf(iy);
        const int x0 = (int)fix, y0 = (int)fiy;
        const float fx = ix - fix;
        const float fy = iy - fiy;

        const bool vx0 = (x0 >= 0)  & (x0 < W);
        const bool vx1 = (x0 >= -1) & (x0 < W - 1);
        const bool vy0 = (y0 >= 0)  & (y0 < W);
        const bool vy1 = (y0 >= -1) & (y0 < W - 1);

        const int xc0 = min(max(x0, 0),     W - 1);
        const int xc1 = min(max(x0 + 1, 0), W - 1);
        const int yc0 = min(max(y0, 0),     W - 1);
        const int yc1 = min(max(y0 + 1, 0), W - 1);

        const int base = b * S_ + st;
        const int i00 = (base + yc0 * W + xc0) * DM;
        const int i01 = (base + yc0 * W + xc1) * DM;
        const int i10 = (base + yc1 * W + xc0) * DM;
        const int i11 = (base + yc1 * W + xc1) * DM;

        const float fx0 = vx0 ? (1.f - fx) : 0.f;
        const float fx1 = vx1 ? fx         : 0.f;
        const float fy0 = (vy0 ? (1.f - fy) : 0.f) * wt;
        const float fy1 = (vy1 ? fy         : 0.f) * wt;

        int2* d = sdw + t * 4;
        d[0] = make_int2(i00, __float_as_int(fx0 * fy0));
        d[1] = make_int2(i01, __float_as_int(fx1 * fy0));
        d[2] = make_int2(i10, __float_as_int(fx0 * fy1));
        d[3] = make_int2(i11, __float_as_int(fx1 * fy1));
    }
    __syncthreads();

    // gather: warp = head; lane = 8*corner + channel-quad
    const int h    = t >> 5;
    const int lane = t & 31;
    const int g = lane >> 3;        // corner 0..3
    const int r = lane & 7;         // channel quad 0..7

    const float* vch = val + h * HD + 4 * r;
    const int2* dbase = sdw + h * TOTAL * 4 + g;

    float4 acc = make_float4(0.f, 0.f, 0.f, 0.f);

    #pragma unroll
    for (int p0 = 0; p0 < TOTAL; p0 += 4) {
        int2 dw[4];
        #pragma unroll
        for (int j = 0; j < 4; j++) dw[j] = dbase[(p0 + j) * 4];

        float4 v[4];
        #pragma unroll
        for (int j = 0; j < 4; j++) v[j] = __ldg((const float4*)(vch + dw[j].x));

        #pragma unroll
        for (int j = 0; j < 4; j++) {
            const float wg = __int_as_float(dw[j].y);
            acc.x = fmaf(wg, v[j].x, acc.x);
            acc.y = fmaf(wg, v[j].y, acc.y);
            acc.z = fmaf(wg, v[j].z, acc.z);
            acc.w = fmaf(wg, v[j].w, acc.w);
        }
    }

    // reduce across the 4 corner groups
    #pragma unroll
    for (int mask = 8; mask <= 16; mask <<= 1) {
        acc.x += __shfl_xor_sync(0xffffffffu, acc.x, mask);
        acc.y += __shfl_xor_sync(0xffffffffu, acc.y, mask);
        acc.z += __shfl_xor_sync(0xffffffffu, acc.z, mask);
        acc.w += __shfl_xor_sync(0xffffffffu, acc.w, mask);
    }

    if (lane < 8)
        *(float4*)(out + (size_t)bq * DM + h * HD + 4 * lane) = acc;
}

// ---------------------------------------------------------------------------
// Launch
// ---------------------------------------------------------------------------
extern "C" void kernel_launch(void* const* d_in, const int* in_sizes, int n_in,
                              void* d_out, int out_size)
{
    const float* query = (const float*)d_in[0];
    const float* ref   = (const float*)d_in[1];
    const float* value = (const float*)d_in[2];
    const float* Woff  = (const float*)d_in[3];
    const float* boff  = (const float*)d_in[4];
    const float* Wattn = (const float*)d_in[5];
    const float* battn = (const float*)d_in[6];
    float* out = (float*)d_out;

    dim3 ggrid(B_ * LQ / BM, 3);                     // 150 x 3
    gemm_kernel<<<ggrid, 256>>>(query, Woff, boff, Wattn, battn);

    sample_kernel<<<B_ * LQ, 256>>>(value, ref, out);   // 9600 blocks, 1 bq each
}